// round 7
// baseline (speedup 1.0000x reference)
#include <cuda_runtime.h>
#include <cstdint>

// Problem constants
#define T_ 1024
#define K_ 2
#define E_ 8
#define H_ 2048
#define I_ 1024

#define BM 128
#define KC 16            // K chunk (tf32 elements)
#define KP 20            // padded row stride (words): bank = (20r + c) mod 32 -> conflict-free
#define THREADS 256
#define MAX_TILES 24

// Scratch (device globals — allocation is forbidden)
__device__ int   g_pair_src[T_ * K_];
__device__ int   g_tile_e[MAX_TILES];
__device__ int   g_tile_start[MAX_TILES];
__device__ int   g_tile_cnt[MAX_TILES];
__device__ int   g_num_tiles;
__device__ float g_inter[(size_t)T_ * K_ * I_];   // 8 MB fp32 intermediate

// ---------------------------------------------------------------- helpers
__device__ __forceinline__ uint32_t f2tf32(float f) {
    uint32_t r; asm("cvt.rna.tf32.f32 %0, %1;" : "=r"(r) : "f"(f)); return r;
}
__device__ __forceinline__ uint4 q2tf32(float4 v) {
    return make_uint4(f2tf32(v.x), f2tf32(v.y), f2tf32(v.z), f2tf32(v.w));
}

__device__ __forceinline__ void mma_tf32(float* c, const uint32_t* a, const uint32_t* b) {
    asm volatile(
        "mma.sync.aligned.m16n8k8.row.col.f32.tf32.tf32.f32 "
        "{%0,%1,%2,%3}, {%4,%5,%6,%7}, {%8,%9}, {%0,%1,%2,%3};"
        : "+f"(c[0]), "+f"(c[1]), "+f"(c[2]), "+f"(c[3])
        : "r"(a[0]), "r"(a[1]), "r"(a[2]), "r"(a[3]), "r"(b[0]), "r"(b[1]));
}

__device__ __forceinline__ float silu(float x) {
    return x / (1.f + __expf(-x));
}

__device__ __forceinline__ float4 ldg4(const float* p) {
    return __ldg((const float4*)p);
}

// ---------------------------------------------------------------- routing
__global__ void route_kernel(const int* __restrict__ sel) {
    __shared__ int cnt[E_], cur[E_];
    int tid = threadIdx.x;
    if (tid < E_) cnt[tid] = 0;
    __syncthreads();
    for (int i = tid; i < T_ * K_; i += blockDim.x) {
        int e = min(max(sel[i], 0), E_ - 1);
        atomicAdd(&cnt[e], 1);
    }
    __syncthreads();
    if (tid == 0) {
        int off = 0, nt = 0;
        for (int e = 0; e < E_; e++) {
            cur[e] = off;
            for (int m = 0; m < cnt[e] && nt < MAX_TILES; m += BM) {
                g_tile_e[nt] = e;
                g_tile_start[nt] = off + m;
                g_tile_cnt[nt] = min(BM, cnt[e] - m);
                nt++;
            }
            off += cnt[e];
        }
        g_num_tiles = nt;
    }
    __syncthreads();
    for (int i = tid; i < T_ * K_; i += blockDim.x) {
        int e = min(max(sel[i], 0), E_ - 1);
        int pos = atomicAdd(&cur[e], 1);
        if (pos < T_ * K_) g_pair_src[pos] = i;   // i = t*K + slot; output row == i
    }
}

// ---------------------------------------------------------------- GEMM1
// inter[pair, n] = silu(x.Wg^T[n]) * (x.Wu^T[n]); CTA: 128 pairs x 64 n-cols.
// C tile 128x128: cols 0..63 = gate(nblk*64..), cols 64..127 = up(same).
__global__ void __launch_bounds__(THREADS, 2)
gemm1_kernel(const float* __restrict__ hs, const float* __restrict__ wgu) {
    const int tile = blockIdx.x;
    if (tile >= g_num_tiles) return;
    const int nblk = blockIdx.y;                 // 0..15  (I/64)
    const int e     = g_tile_e[tile];
    const int start = g_tile_start[tile];
    const int cnt   = g_tile_cnt[tile];
    const int tid = threadIdx.x, wid = tid >> 5, lane = tid & 31;
    const int wm = wid & 3, wn = wid >> 2;
    const int g = lane >> 2, t = lane & 3;

    __shared__ uint32_t As[2][BM][KP];
    __shared__ uint32_t Bs[2][BM][KP];
    __shared__ int s_tok[BM];

    if (tid < BM) {
        int v = (tid < cnt) ? g_pair_src[start + tid] : 0;
        s_tok[tid] = v / K_;
    }
    __syncthreads();

    const float* wb = wgu + (size_t)e * (2 * I_) * H_;
    // Loader mapping: each thread owns row (tid&127), half (tid>>7) of 16 cols
    const int srow = tid & 127, shalf = tid >> 7;
    const int wrow = (srow < 64) ? (nblk * 64 + srow) : (I_ + nblk * 64 + srow - 64);
    const float* arow = hs + (size_t)s_tok[srow] * H_ + shalf * 8;
    const float* brow = wb + (size_t)wrow * H_ + shalf * 8;
    const bool arow_ok = (srow < cnt);

    float acc[2][8][4];
#pragma unroll
    for (int mb = 0; mb < 2; mb++)
#pragma unroll
        for (int nb = 0; nb < 8; nb++)
#pragma unroll
            for (int i = 0; i < 4; i++) acc[mb][nb][i] = 0.f;

    float4 ra[2], rb[2];
    // prefetch chunk 0 and fill stage 0
#pragma unroll
    for (int q = 0; q < 2; q++) {
        ra[q] = arow_ok ? ldg4(arow + q * 4) : make_float4(0.f, 0.f, 0.f, 0.f);
        rb[q] = ldg4(brow + q * 4);
    }
#pragma unroll
    for (int q = 0; q < 2; q++) {
        *(uint4*)&As[0][srow][shalf * 8 + q * 4] = q2tf32(ra[q]);
        *(uint4*)&Bs[0][srow][shalf * 8 + q * 4] = q2tf32(rb[q]);
    }
    __syncthreads();

    const int NK = H_ / KC;
#pragma unroll 1
    for (int kk = 0; kk < NK; kk++) {
        const int buf = kk & 1;
        // prefetch next chunk into registers
        if (kk + 1 < NK) {
            const int ko = (kk + 1) * KC;
#pragma unroll
            for (int q = 0; q < 2; q++) {
                ra[q] = arow_ok ? ldg4(arow + ko + q * 4) : make_float4(0.f, 0.f, 0.f, 0.f);
                rb[q] = ldg4(brow + ko + q * 4);
            }
        }
        // compute current chunk (conflict-free fragment LDS)
#pragma unroll
        for (int ks = 0; ks < 2; ks++) {
            const int k0 = ks * 8;
            uint32_t af[2][4];
#pragma unroll
            for (int mb = 0; mb < 2; mb++) {
                int r = wm * 32 + mb * 16 + g;
                af[mb][0] = As[buf][r][k0 + t];
                af[mb][1] = As[buf][r + 8][k0 + t];
                af[mb][2] = As[buf][r][k0 + t + 4];
                af[mb][3] = As[buf][r + 8][k0 + t + 4];
            }
            uint32_t bf[8][2];
#pragma unroll
            for (int nb = 0; nb < 8; nb++) {
                int cb = (nb < 4) ? (wn * 32 + nb * 8) : (64 + wn * 32 + (nb - 4) * 8);
                bf[nb][0] = Bs[buf][cb + g][k0 + t];
                bf[nb][1] = Bs[buf][cb + g][k0 + t + 4];
            }
#pragma unroll
            for (int mb = 0; mb < 2; mb++)
#pragma unroll
                for (int nb = 0; nb < 8; nb++)
                    mma_tf32(acc[mb][nb], af[mb], bf[nb]);
        }
        // stage next chunk into the other buffer
        if (kk + 1 < NK) {
            const int nb2 = buf ^ 1;
#pragma unroll
            for (int q = 0; q < 2; q++) {
                *(uint4*)&As[nb2][srow][shalf * 8 + q * 4] = q2tf32(ra[q]);
                *(uint4*)&Bs[nb2][srow][shalf * 8 + q * 4] = q2tf32(rb[q]);
            }
        }
        __syncthreads();
    }

    // epilogue: silu(gate)*up -> g_inter
#pragma unroll
    for (int mb = 0; mb < 2; mb++) {
        int r0 = wm * 32 + mb * 16 + g;
#pragma unroll
        for (int nb = 0; nb < 4; nb++) {
            int col = nblk * 64 + wn * 32 + nb * 8 + 2 * t;
            const float* cg = acc[mb][nb];
            const float* cu = acc[mb][nb + 4];
            if (r0 < cnt) {
                float2 v = make_float2(silu(cg[0]) * cu[0], silu(cg[1]) * cu[1]);
                *(float2*)(g_inter + (size_t)(start + r0) * I_ + col) = v;
            }
            if (r0 + 8 < cnt) {
                float2 v = make_float2(silu(cg[2]) * cu[2], silu(cg[3]) * cu[3]);
                *(float2*)(g_inter + (size_t)(start + r0 + 8) * I_ + col) = v;
            }
        }
    }
}

// ---------------------------------------------------------------- GEMM2
// out[src(pair), h] = inter[pair, :] . down[e, h, :]; CTA: 128 pairs x 128 h.
__global__ void __launch_bounds__(THREADS, 2)
gemm2_kernel(const float* __restrict__ dn, float* __restrict__ out) {
    const int tile = blockIdx.x;
    if (tile >= g_num_tiles) return;
    const int nblk = blockIdx.y;                 // 0..15  (H/128)
    const int e     = g_tile_e[tile];
    const int start = g_tile_start[tile];
    const int cnt   = g_tile_cnt[tile];
    const int tid = threadIdx.x, wid = tid >> 5, lane = tid & 31;
    const int wm = wid & 3, wn = wid >> 2;
    const int g = lane >> 2, t = lane & 3;

    __shared__ uint32_t As[2][BM][KP];
    __shared__ uint32_t Bs[2][BM][KP];
    __shared__ int s_src[BM];

    if (tid < BM)
        s_src[tid] = (tid < cnt) ? g_pair_src[start + tid] : 0;
    __syncthreads();

    const float* wb = dn + ((size_t)e * H_ + (size_t)nblk * 128) * I_;
    const int srow = tid & 127, shalf = tid >> 7;
    const float* arow = g_inter + (size_t)(start + srow) * I_ + shalf * 8;
    const float* brow = wb + (size_t)srow * I_ + shalf * 8;
    const bool arow_ok = (srow < cnt);

    float acc[2][8][4];
#pragma unroll
    for (int mb = 0; mb < 2; mb++)
#pragma unroll
        for (int nb = 0; nb < 8; nb++)
#pragma unroll
            for (int i = 0; i < 4; i++) acc[mb][nb][i] = 0.f;

    float4 ra[2], rb[2];
#pragma unroll
    for (int q = 0; q < 2; q++) {
        ra[q] = arow_ok ? ldg4(arow + q * 4) : make_float4(0.f, 0.f, 0.f, 0.f);
        rb[q] = ldg4(brow + q * 4);
    }
#pragma unroll
    for (int q = 0; q < 2; q++) {
        *(uint4*)&As[0][srow][shalf * 8 + q * 4] = q2tf32(ra[q]);
        *(uint4*)&Bs[0][srow][shalf * 8 + q * 4] = q2tf32(rb[q]);
    }
    __syncthreads();

    const int NK = I_ / KC;
#pragma unroll 1
    for (int kk = 0; kk < NK; kk++) {
        const int buf = kk & 1;
        if (kk + 1 < NK) {
            const int ko = (kk + 1) * KC;
#pragma unroll
            for (int q = 0; q < 2; q++) {
                ra[q] = arow_ok ? ldg4(arow + ko + q * 4) : make_float4(0.f, 0.f, 0.f, 0.f);
                rb[q] = ldg4(brow + ko + q * 4);
            }
        }
#pragma unroll
        for (int ks = 0; ks < 2; ks++) {
            const int k0 = ks * 8;
            uint32_t af[2][4];
#pragma unroll
            for (int mb = 0; mb < 2; mb++) {
                int r = wm * 32 + mb * 16 + g;
                af[mb][0] = As[buf][r][k0 + t];
                af[mb][1] = As[buf][r + 8][k0 + t];
                af[mb][2] = As[buf][r][k0 + t + 4];
                af[mb][3] = As[buf][r + 8][k0 + t + 4];
            }
            uint32_t bf[8][2];
#pragma unroll
            for (int nb = 0; nb < 8; nb++) {
                int cb = wn * 64 + nb * 8;
                bf[nb][0] = Bs[buf][cb + g][k0 + t];
                bf[nb][1] = Bs[buf][cb + g][k0 + t + 4];
            }
#pragma unroll
            for (int mb = 0; mb < 2; mb++)
#pragma unroll
                for (int nb = 0; nb < 8; nb++)
                    mma_tf32(acc[mb][nb], af[mb], bf[nb]);
        }
        if (kk + 1 < NK) {
            const int nb2 = buf ^ 1;
#pragma unroll
            for (int q = 0; q < 2; q++) {
                *(uint4*)&As[nb2][srow][shalf * 8 + q * 4] = q2tf32(ra[q]);
                *(uint4*)&Bs[nb2][srow][shalf * 8 + q * 4] = q2tf32(rb[q]);
            }
        }
        __syncthreads();
    }

    // epilogue: scatter rows to out[src]
#pragma unroll
    for (int mb = 0; mb < 2; mb++) {
        int r0 = wm * 32 + mb * 16 + g;
        int src0 = s_src[r0 & (BM - 1)];
        int src1 = s_src[(r0 + 8) & (BM - 1)];
#pragma unroll
        for (int nb = 0; nb < 8; nb++) {
            int col = nblk * 128 + wn * 64 + nb * 8 + 2 * t;
            const float* c = acc[mb][nb];
            if (r0 < cnt)
                *(float2*)(out + (size_t)src0 * H_ + col) = make_float2(c[0], c[1]);
            if (r0 + 8 < cnt)
                *(float2*)(out + (size_t)src1 * H_ + col) = make_float2(c[2], c[3]);
        }
    }
}

// ---------------------------------------------------------------- launch
extern "C" void kernel_launch(void* const* d_in, const int* in_sizes, int n_in,
                              void* d_out, int out_size) {
    // Identify inputs by element count (robust to metadata ordering):
    //   hidden_states: T*H     = 2,097,152 f32
    //   selected:      T*K     = 2,048 i32
    //   gate_up_proj:  E*2I*H  = 33,554,432 f32
    //   down_proj:     E*H*I   = 16,777,216 f32
    const float* hs  = nullptr;
    const int*   sel = nullptr;
    const float* wgu = nullptr;
    const float* dn  = nullptr;
    for (int i = 0; i < n_in; i++) {
        long long n = in_sizes[i];
        if (n == (long long)T_ * H_)               hs  = (const float*)d_in[i];
        else if (n == (long long)T_ * K_)          sel = (const int*)d_in[i];
        else if (n == (long long)E_ * 2 * I_ * H_) wgu = (const float*)d_in[i];
        else if (n == (long long)E_ * H_ * I_)     dn  = (const float*)d_in[i];
    }
    float* out = (float*)d_out;
    if (!hs || !sel || !wgu || !dn) return;

    route_kernel<<<1, 256>>>(sel);
    gemm1_kernel<<<dim3(MAX_TILES, I_ / 64), THREADS>>>(hs, wgu);
    gemm2_kernel<<<dim3(MAX_TILES, H_ / 128), THREADS>>>(dn, out);
}

// round 9
// speedup vs baseline: 1.8597x; 1.8597x over previous
#include <cuda_runtime.h>
#include <cstdint>

// Problem constants
#define T_ 1024
#define K_ 2
#define E_ 8
#define H_ 2048
#define I_ 1024

#define BM 128
#define KC 32            // K chunk (tf32 elements)
#define KP 36            // padded row stride (words): bank = (4r + c) mod 32 -> conflict-free
#define THREADS 256
#define MAX_TILES 24
#define STAGES 3
#define SBW (BM * KP)                 // words per tile buffer
#define SMEM_BYTES (2 * STAGES * SBW * 4)   // As + Bs, 110592 bytes

// Scratch (device globals — allocation is forbidden)
__device__ int   g_pair_src[T_ * K_];
__device__ int   g_tile_e[MAX_TILES];
__device__ int   g_tile_start[MAX_TILES];
__device__ int   g_tile_cnt[MAX_TILES];
__device__ int   g_num_tiles;
__device__ float g_inter[(size_t)T_ * K_ * I_];   // 8 MB fp32 intermediate

// ---------------------------------------------------------------- helpers
__device__ __forceinline__ uint32_t f2tf32(float f) {
    uint32_t r; asm("cvt.rna.tf32.f32 %0, %1;" : "=r"(r) : "f"(f)); return r;
}
__device__ __forceinline__ uint32_t lds_tf32(const uint32_t* p) {
    return f2tf32(__uint_as_float(*p));
}

__device__ __forceinline__ void cp16(uint32_t dst, const void* src, int srcsize) {
    asm volatile("cp.async.cg.shared.global [%0], [%1], 16, %2;"
                 :: "r"(dst), "l"(src), "r"(srcsize));
}
#define CP_COMMIT()  asm volatile("cp.async.commit_group;")
#define CP_WAIT1()   asm volatile("cp.async.wait_group 1;")

__device__ __forceinline__ void mma_tf32(float* c, const uint32_t* a, const uint32_t* b) {
    asm volatile(
        "mma.sync.aligned.m16n8k8.row.col.f32.tf32.tf32.f32 "
        "{%0,%1,%2,%3}, {%4,%5,%6,%7}, {%8,%9}, {%0,%1,%2,%3};"
        : "+f"(c[0]), "+f"(c[1]), "+f"(c[2]), "+f"(c[3])
        : "r"(a[0]), "r"(a[1]), "r"(a[2]), "r"(a[3]), "r"(b[0]), "r"(b[1]));
}

__device__ __forceinline__ float silu(float x) {
    return x / (1.f + __expf(-x));
}

// ---------------------------------------------------------------- routing
__global__ void route_kernel(const int* __restrict__ sel) {
    __shared__ int cnt[E_], cur[E_];
    int tid = threadIdx.x;
    if (tid < E_) cnt[tid] = 0;
    __syncthreads();
    for (int i = tid; i < T_ * K_; i += blockDim.x) {
        int e = min(max(sel[i], 0), E_ - 1);
        atomicAdd(&cnt[e], 1);
    }
    __syncthreads();
    if (tid == 0) {
        int off = 0, nt = 0;
        for (int e = 0; e < E_; e++) {
            cur[e] = off;
            for (int m = 0; m < cnt[e] && nt < MAX_TILES; m += BM) {
                g_tile_e[nt] = e;
                g_tile_start[nt] = off + m;
                g_tile_cnt[nt] = min(BM, cnt[e] - m);
                nt++;
            }
            off += cnt[e];
        }
        g_num_tiles = nt;
    }
    __syncthreads();
    for (int i = tid; i < T_ * K_; i += blockDim.x) {
        int e = min(max(sel[i], 0), E_ - 1);
        int pos = atomicAdd(&cur[e], 1);
        if (pos < T_ * K_) g_pair_src[pos] = i;   // i = t*K + slot; output row == i
    }
}

// ---------------------------------------------------------------- GEMM1
// inter[pair, n] = silu(x.Wg^T[n]) * (x.Wu^T[n]); CTA: 128 pairs x 64 n-cols.
// C tile 128x128: cols 0..63 = gate(nblk*64..), cols 64..127 = up(same).
__global__ void __launch_bounds__(THREADS, 2)
gemm1_kernel(const float* __restrict__ hs, const float* __restrict__ wgu) {
    const int tile = blockIdx.x;
    if (tile >= g_num_tiles) return;
    const int nblk = blockIdx.y;                 // 0..15  (I/64)
    const int e     = g_tile_e[tile];
    const int start = g_tile_start[tile];
    const int cnt   = g_tile_cnt[tile];
    const int tid = threadIdx.x, wid = tid >> 5, lane = tid & 31;
    const int wm = wid & 3, wn = wid >> 2;
    const int g = lane >> 2, t = lane & 3;

    extern __shared__ uint32_t sm[];
    uint32_t* Asm = sm;               // [STAGES][BM][KP]
    uint32_t* Bsm = sm + STAGES * SBW;
    __shared__ int s_tok[BM];

    if (tid < BM) {
        int v = (tid < cnt) ? g_pair_src[start + tid] : 0;
        s_tok[tid] = v / K_;
    }
    __syncthreads();

    const float* wb = wgu + (size_t)e * (2 * I_) * H_;

    // cp.async assignments: idx = tid + j*256 -> row = idx>>3, quad = idx&7
    uint32_t a_dst[4], b_dst[4];
    const float* a_src[4];
    const float* b_src[4];
    int a_sz[4];
#pragma unroll
    for (int j = 0; j < 4; j++) {
        int idx = tid + j * THREADS;
        int r = idx >> 3, q = idx & 7;
        a_dst[j] = (uint32_t)__cvta_generic_to_shared(&Asm[r * KP + q * 4]);
        b_dst[j] = (uint32_t)__cvta_generic_to_shared(&Bsm[r * KP + q * 4]);
        a_src[j] = hs + (size_t)s_tok[r] * H_ + q * 4;
        int wr = (r < 64) ? (nblk * 64 + r) : (I_ + nblk * 64 + r - 64);
        b_src[j] = wb + (size_t)wr * H_ + q * 4;
        a_sz[j] = (r < cnt) ? 16 : 0;
    }

    float acc[2][8][4];
#pragma unroll
    for (int mb = 0; mb < 2; mb++)
#pragma unroll
        for (int nb = 0; nb < 8; nb++)
#pragma unroll
            for (int i = 0; i < 4; i++) acc[mb][nb][i] = 0.f;

    const int NK = H_ / KC;
    // prologue: stages 0,1 in flight
#pragma unroll
    for (int s = 0; s < STAGES - 1; s++) {
        const uint32_t boff = (uint32_t)s * SBW * 4;
#pragma unroll
        for (int j = 0; j < 4; j++) {
            cp16(a_dst[j] + boff, a_src[j] + s * KC, a_sz[j]);
            cp16(b_dst[j] + boff, b_src[j] + s * KC, 16);
        }
        CP_COMMIT();
    }

#pragma unroll 1
    for (int kk = 0; kk < NK; kk++) {
        CP_WAIT1();
        __syncthreads();
        const uint32_t* Ab = Asm + (kk % STAGES) * SBW;
        const uint32_t* Bb = Bsm + (kk % STAGES) * SBW;
#pragma unroll
        for (int ks = 0; ks < 4; ks++) {
            const int k0 = ks * 8;
            uint32_t af[2][4];
#pragma unroll
            for (int mb = 0; mb < 2; mb++) {
                int r = wm * 32 + mb * 16 + g;
                af[mb][0] = lds_tf32(&Ab[r * KP + k0 + t]);
                af[mb][1] = lds_tf32(&Ab[(r + 8) * KP + k0 + t]);
                af[mb][2] = lds_tf32(&Ab[r * KP + k0 + t + 4]);
                af[mb][3] = lds_tf32(&Ab[(r + 8) * KP + k0 + t + 4]);
            }
            uint32_t bf[8][2];
#pragma unroll
            for (int nb = 0; nb < 8; nb++) {
                int cb = (nb < 4) ? (wn * 32 + nb * 8) : (64 + wn * 32 + (nb - 4) * 8);
                bf[nb][0] = lds_tf32(&Bb[(cb + g) * KP + k0 + t]);
                bf[nb][1] = lds_tf32(&Bb[(cb + g) * KP + k0 + t + 4]);
            }
#pragma unroll
            for (int mb = 0; mb < 2; mb++)
#pragma unroll
                for (int nb = 0; nb < 8; nb++)
                    mma_tf32(acc[mb][nb], af[mb], bf[nb]);
        }
        // issue chunk kk+2 into buffer (kk+2)%3 == (kk-1)%3 (safe: barrier above
        // guarantees all warps finished computing chunk kk-1)
        const int nc = kk + STAGES - 1;
        if (nc < NK) {
            const uint32_t boff = (uint32_t)(nc % STAGES) * SBW * 4;
#pragma unroll
            for (int j = 0; j < 4; j++) {
                cp16(a_dst[j] + boff, a_src[j] + nc * KC, a_sz[j]);
                cp16(b_dst[j] + boff, b_src[j] + nc * KC, 16);
            }
        }
        CP_COMMIT();
    }

    // epilogue: silu(gate)*up -> g_inter
#pragma unroll
    for (int mb = 0; mb < 2; mb++) {
        int r0 = wm * 32 + mb * 16 + g;
#pragma unroll
        for (int nb = 0; nb < 4; nb++) {
            int col = nblk * 64 + wn * 32 + nb * 8 + 2 * t;
            const float* cg = acc[mb][nb];
            const float* cu = acc[mb][nb + 4];
            if (r0 < cnt) {
                float2 v = make_float2(silu(cg[0]) * cu[0], silu(cg[1]) * cu[1]);
                *(float2*)(g_inter + (size_t)(start + r0) * I_ + col) = v;
            }
            if (r0 + 8 < cnt) {
                float2 v = make_float2(silu(cg[2]) * cu[2], silu(cg[3]) * cu[3]);
                *(float2*)(g_inter + (size_t)(start + r0 + 8) * I_ + col) = v;
            }
        }
    }
}

// ---------------------------------------------------------------- GEMM2
// out[src(pair), h] = inter[pair, :] . down[e, h, :]; CTA: 128 pairs x 128 h.
__global__ void __launch_bounds__(THREADS, 2)
gemm2_kernel(const float* __restrict__ dn, float* __restrict__ out) {
    const int tile = blockIdx.x;
    if (tile >= g_num_tiles) return;
    const int nblk = blockIdx.y;                 // 0..15  (H/128)
    const int e     = g_tile_e[tile];
    const int start = g_tile_start[tile];
    const int cnt   = g_tile_cnt[tile];
    const int tid = threadIdx.x, wid = tid >> 5, lane = tid & 31;
    const int wm = wid & 3, wn = wid >> 2;
    const int g = lane >> 2, t = lane & 3;

    extern __shared__ uint32_t sm[];
    uint32_t* Asm = sm;
    uint32_t* Bsm = sm + STAGES * SBW;
    __shared__ int s_src[BM];

    if (tid < BM)
        s_src[tid] = (tid < cnt) ? g_pair_src[start + tid] : 0;
    __syncthreads();

    const float* wb = dn + ((size_t)e * H_ + (size_t)nblk * 128) * I_;

    uint32_t a_dst[4], b_dst[4];
    const float* a_src[4];
    const float* b_src[4];
    int a_sz[4];
#pragma unroll
    for (int j = 0; j < 4; j++) {
        int idx = tid + j * THREADS;
        int r = idx >> 3, q = idx & 7;
        a_dst[j] = (uint32_t)__cvta_generic_to_shared(&Asm[r * KP + q * 4]);
        b_dst[j] = (uint32_t)__cvta_generic_to_shared(&Bsm[r * KP + q * 4]);
        a_src[j] = g_inter + (size_t)(start + ((r < cnt) ? r : 0)) * I_ + q * 4;
        b_src[j] = wb + (size_t)r * I_ + q * 4;
        a_sz[j] = (r < cnt) ? 16 : 0;
    }

    float acc[2][8][4];
#pragma unroll
    for (int mb = 0; mb < 2; mb++)
#pragma unroll
        for (int nb = 0; nb < 8; nb++)
#pragma unroll
            for (int i = 0; i < 4; i++) acc[mb][nb][i] = 0.f;

    const int NK = I_ / KC;
#pragma unroll
    for (int s = 0; s < STAGES - 1; s++) {
        const uint32_t boff = (uint32_t)s * SBW * 4;
#pragma unroll
        for (int j = 0; j < 4; j++) {
            cp16(a_dst[j] + boff, a_src[j] + s * KC, a_sz[j]);
            cp16(b_dst[j] + boff, b_src[j] + s * KC, 16);
        }
        CP_COMMIT();
    }

#pragma unroll 1
    for (int kk = 0; kk < NK; kk++) {
        CP_WAIT1();
        __syncthreads();
        const uint32_t* Ab = Asm + (kk % STAGES) * SBW;
        const uint32_t* Bb = Bsm + (kk % STAGES) * SBW;
#pragma unroll
        for (int ks = 0; ks < 4; ks++) {
            const int k0 = ks * 8;
            uint32_t af[2][4];
#pragma unroll
            for (int mb = 0; mb < 2; mb++) {
                int r = wm * 32 + mb * 16 + g;
                af[mb][0] = lds_tf32(&Ab[r * KP + k0 + t]);
                af[mb][1] = lds_tf32(&Ab[(r + 8) * KP + k0 + t]);
                af[mb][2] = lds_tf32(&Ab[r * KP + k0 + t + 4]);
                af[mb][3] = lds_tf32(&Ab[(r + 8) * KP + k0 + t + 4]);
            }
            uint32_t bf[8][2];
#pragma unroll
            for (int nb = 0; nb < 8; nb++) {
                int cb = wn * 64 + nb * 8;
                bf[nb][0] = lds_tf32(&Bb[(cb + g) * KP + k0 + t]);
                bf[nb][1] = lds_tf32(&Bb[(cb + g) * KP + k0 + t + 4]);
            }
#pragma unroll
            for (int mb = 0; mb < 2; mb++)
#pragma unroll
                for (int nb = 0; nb < 8; nb++)
                    mma_tf32(acc[mb][nb], af[mb], bf[nb]);
        }
        const int nc = kk + STAGES - 1;
        if (nc < NK) {
            const uint32_t boff = (uint32_t)(nc % STAGES) * SBW * 4;
#pragma unroll
            for (int j = 0; j < 4; j++) {
                cp16(a_dst[j] + boff, a_src[j] + nc * KC, a_sz[j]);
                cp16(b_dst[j] + boff, b_src[j] + nc * KC, 16);
            }
        }
        CP_COMMIT();
    }

    // epilogue: scatter rows to out[src]
#pragma unroll
    for (int mb = 0; mb < 2; mb++) {
        int r0 = wm * 32 + mb * 16 + g;
        int src0 = s_src[r0 & (BM - 1)];
        int src1 = s_src[(r0 + 8) & (BM - 1)];
#pragma unroll
        for (int nb = 0; nb < 8; nb++) {
            int col = nblk * 128 + wn * 64 + nb * 8 + 2 * t;
            const float* c = acc[mb][nb];
            if (r0 < cnt)
                *(float2*)(out + (size_t)src0 * H_ + col) = make_float2(c[0], c[1]);
            if (r0 + 8 < cnt)
                *(float2*)(out + (size_t)src1 * H_ + col) = make_float2(c[2], c[3]);
        }
    }
}

// ---------------------------------------------------------------- launch
extern "C" void kernel_launch(void* const* d_in, const int* in_sizes, int n_in,
                              void* d_out, int out_size) {
    // Identify inputs by element count (robust to metadata ordering)
    const float* hs  = nullptr;
    const int*   sel = nullptr;
    const float* wgu = nullptr;
    const float* dn  = nullptr;
    for (int i = 0; i < n_in; i++) {
        long long n = in_sizes[i];
        if (n == (long long)T_ * H_)               hs  = (const float*)d_in[i];
        else if (n == (long long)T_ * K_)          sel = (const int*)d_in[i];
        else if (n == (long long)E_ * 2 * I_ * H_) wgu = (const float*)d_in[i];
        else if (n == (long long)E_ * H_ * I_)     dn  = (const float*)d_in[i];
    }
    float* out = (float*)d_out;
    if (!hs || !sel || !wgu || !dn) return;

    cudaFuncSetAttribute(gemm1_kernel, cudaFuncAttributeMaxDynamicSharedMemorySize, SMEM_BYTES);
    cudaFuncSetAttribute(gemm2_kernel, cudaFuncAttributeMaxDynamicSharedMemorySize, SMEM_BYTES);

    route_kernel<<<1, 256>>>(sel);
    gemm1_kernel<<<dim3(MAX_TILES, I_ / 64), THREADS, SMEM_BYTES>>>(hs, wgu);
    gemm2_kernel<<<dim3(MAX_TILES, H_ / 128), THREADS, SMEM_BYTES>>>(dn, out);
}